// round 3
// baseline (speedup 1.0000x reference)
#include <cuda_runtime.h>

#define N_NODES 50000
#define N_EDGES 1600000
#define N_LABEL 200000
#define IN_C    128
#define HID1    256
#define HID2    32

// ---------------- device scratch (no allocations allowed) ----------------
__device__ __align__(256) float g_deg [N_NODES];
__device__ __align__(256) float g_dinv[N_NODES];
__device__ __align__(256) float g_xs  [N_NODES * IN_C];   // dinv[i]*x[i]
__device__ __align__(256) float g_S1  [N_NODES * IN_C];   // sum_{edges+self} xs[src]
__device__ __align__(256) float g_h1  [N_NODES * HID1];   // relu(dinv*S1@W1 + b1)
__device__ __align__(256) float g_ts  [N_NODES * HID2];   // dinv[i]*(h1@W2)
__device__ __align__(256) float g_S2  [N_NODES * HID2];
__device__ __align__(256) float g_z   [N_NODES * HID2];

// ---------------- degree / normalization ----------------
__global__ void k_deg_init() {
    int i = blockIdx.x * blockDim.x + threadIdx.x;
    if (i < N_NODES) g_deg[i] = 1.0f;               // self-loop
}

__global__ void k_deg_count(const int* __restrict__ ei) {
    int e = blockIdx.x * blockDim.x + threadIdx.x;
    if (e < N_EDGES) atomicAdd(&g_deg[ei[N_EDGES + e]], 1.0f);
}

__global__ void k_dinv() {
    int i = blockIdx.x * blockDim.x + threadIdx.x;
    if (i < N_NODES) g_dinv[i] = rsqrtf(g_deg[i]);
}

// xs = dinv[i]*x[i]; seed S1 with self-loop term (xs itself)
__global__ void k_scale_seed(const float* __restrict__ x) {
    int t = blockIdx.x * blockDim.x + threadIdx.x;       // over N_NODES*32 float4s
    if (t < N_NODES * (IN_C / 4)) {
        int i = t / (IN_C / 4);
        float di = g_dinv[i];
        float4 v = ((const float4*)x)[t];
        v.x *= di; v.y *= di; v.z *= di; v.w *= di;
        ((float4*)g_xs)[t] = v;
        ((float4*)g_S1)[t] = v;
    }
}

// ---------------- conv1 scatter: S1[dst] += xs[src]
// one warp per edge: 32 lanes x float4 gather -> 4 scalar REDs each
__global__ void k_scatter1(const int* __restrict__ ei) {
    unsigned t = blockIdx.x * blockDim.x + threadIdx.x;
    unsigned e = t >> 5;
    if (e >= N_EDGES) return;
    int lane = t & 31;
    int src = ei[e];                      // broadcast load across warp
    int dst = ei[N_EDGES + e];
    float4 v = ((const float4*)g_xs)[src * 32 + lane];
    float* d = g_S1 + dst * IN_C + lane * 4;
    atomicAdd(d + 0, v.x);
    atomicAdd(d + 1, v.y);
    atomicAdd(d + 2, v.z);
    atomicAdd(d + 3, v.w);
}

// ---------------- GEMM1: h1 = relu(dinv[i]*(S1 @ W1) + b1)   [50000x128]x[128x256]
__global__ void k_gemm1(const float* __restrict__ W, const float* __restrict__ b1) {
    __shared__ float As[16][64];   // transposed [k][row]
    __shared__ float Bs[16][64];
    const int tid   = threadIdx.x;
    const int tileM = blockIdx.x * 64;
    const int tileN = blockIdx.y * 64;
    const int tx = tid & 15, ty = tid >> 4;
    const int ar = tid >> 2;           // row in tile 0..63
    const int ac = (tid & 3) * 4;      // k offset within 16
    const int br = tid >> 4;           // k row 0..15
    const int bc = (tid & 15) * 4;     // col offset 0..60
    float acc[4][4] = {};

    for (int k0 = 0; k0 < IN_C; k0 += 16) {
        float4 av = make_float4(0.f, 0.f, 0.f, 0.f);
        int grow = tileM + ar;
        if (grow < N_NODES) av = *(const float4*)&g_S1[grow * IN_C + k0 + ac];
        As[ac + 0][ar] = av.x; As[ac + 1][ar] = av.y;
        As[ac + 2][ar] = av.z; As[ac + 3][ar] = av.w;
        *(float4*)&Bs[br][bc] = *(const float4*)&W[(k0 + br) * HID1 + tileN + bc];
        __syncthreads();
#pragma unroll
        for (int kk = 0; kk < 16; kk++) {
            float4 a  = *(const float4*)&As[kk][ty * 4];
            float4 bb = *(const float4*)&Bs[kk][tx * 4];
            float aa[4] = {a.x, a.y, a.z, a.w};
            float bv[4] = {bb.x, bb.y, bb.z, bb.w};
#pragma unroll
            for (int i = 0; i < 4; i++)
#pragma unroll
                for (int j = 0; j < 4; j++) acc[i][j] += aa[i] * bv[j];
        }
        __syncthreads();
    }

    float4 bcol = *(const float4*)&b1[tileN + tx * 4];
    float bv[4] = {bcol.x, bcol.y, bcol.z, bcol.w};
#pragma unroll
    for (int i = 0; i < 4; i++) {
        int r = tileM + ty * 4 + i;
        if (r < N_NODES) {
            float di = g_dinv[r];
            float4 o;
            o.x = fmaxf(di * acc[i][0] + bv[0], 0.f);
            o.y = fmaxf(di * acc[i][1] + bv[1], 0.f);
            o.z = fmaxf(di * acc[i][2] + bv[2], 0.f);
            o.w = fmaxf(di * acc[i][3] + bv[3], 0.f);
            *(float4*)&g_h1[r * HID1 + tileN + tx * 4] = o;
        }
    }
}

// ---------------- GEMM2: ts = dinv[i]*(h1 @ W2); S2 seeded = ts   [50000x256]x[256x32]
__global__ void k_gemm2(const float* __restrict__ W2) {
    __shared__ float As[128][33];   // padded to kill bank conflicts
    __shared__ float Bs[32][32];
    const int tid   = threadIdx.x;
    const int tileM = blockIdx.x * 128;
    const int tx = tid & 7, ty = tid >> 3;
    float acc[4][4] = {};

    for (int k0 = 0; k0 < HID1; k0 += 32) {
#pragma unroll
        for (int i = 0; i < 4; i++) {
            int idx = tid + i * 256;
            int r   = idx >> 3;
            int c4  = (idx & 7) * 4;
            int grow = tileM + r;
            float4 v = make_float4(0.f, 0.f, 0.f, 0.f);
            if (grow < N_NODES) v = *(const float4*)&g_h1[grow * HID1 + k0 + c4];
            As[r][c4 + 0] = v.x; As[r][c4 + 1] = v.y;
            As[r][c4 + 2] = v.z; As[r][c4 + 3] = v.w;
        }
        {
            int kr = tid >> 3, c4 = (tid & 7) * 4;
            *(float4*)&Bs[kr][c4] = *(const float4*)&W2[(k0 + kr) * HID2 + c4];
        }
        __syncthreads();
#pragma unroll
        for (int kk = 0; kk < 32; kk++) {
            float4 bb = *(const float4*)&Bs[kk][tx * 4];
            float bv[4] = {bb.x, bb.y, bb.z, bb.w};
#pragma unroll
            for (int i = 0; i < 4; i++) {
                float a = As[ty * 4 + i][kk];
#pragma unroll
                for (int j = 0; j < 4; j++) acc[i][j] += a * bv[j];
            }
        }
        __syncthreads();
    }

#pragma unroll
    for (int i = 0; i < 4; i++) {
        int r = tileM + ty * 4 + i;
        if (r < N_NODES) {
            float di = g_dinv[r];
            float4 o = make_float4(di * acc[i][0], di * acc[i][1],
                                   di * acc[i][2], di * acc[i][3]);
            *(float4*)&g_ts[r * HID2 + tx * 4] = o;
            *(float4*)&g_S2[r * HID2 + tx * 4] = o;
        }
    }
}

// ---------------- conv2 scatter: S2[dst] += ts[src]
// 8 lanes per edge: each lane one float4 gather -> 4 scalar REDs
__global__ void k_scatter2(const int* __restrict__ ei) {
    unsigned t = blockIdx.x * blockDim.x + threadIdx.x;
    unsigned e = t >> 3;
    if (e >= N_EDGES) return;
    int j   = t & 7;
    int src = ei[e];
    int dst = ei[N_EDGES + e];
    float4 v = ((const float4*)g_ts)[src * 8 + j];
    float* d = g_S2 + dst * HID2 + j * 4;
    atomicAdd(d + 0, v.x);
    atomicAdd(d + 1, v.y);
    atomicAdd(d + 2, v.z);
    atomicAdd(d + 3, v.w);
}

// ---------------- z = dinv[i]*S2 + b2
__global__ void k_z(const float* __restrict__ b2) {
    int t = blockIdx.x * blockDim.x + threadIdx.x;       // over N_NODES*8 float4s
    if (t < N_NODES * (HID2 / 4)) {
        int i  = t >> 3;
        int c4 = (t & 7) * 4;
        float di = g_dinv[i];
        float4 s  = ((const float4*)g_S2)[t];
        float4 bb = *(const float4*)&b2[c4];
        float4 o  = make_float4(di * s.x + bb.x, di * s.y + bb.y,
                                di * s.z + bb.z, di * s.w + bb.w);
        ((float4*)g_z)[t] = o;
    }
}

// ---------------- decode: out[k] = dot(z[a], z[b]); one warp per label edge
__global__ void k_decode(const int* __restrict__ eli, float* __restrict__ out) {
    int t = blockIdx.x * blockDim.x + threadIdx.x;
    int k = t >> 5;
    if (k >= N_LABEL) return;
    int lane = t & 31;
    int a = eli[k];
    int b = eli[N_LABEL + k];
    float p = g_z[a * 32 + lane] * g_z[b * 32 + lane];
#pragma unroll
    for (int off = 16; off; off >>= 1) p += __shfl_xor_sync(0xffffffffu, p, off);
    if (lane == 0) out[k] = p;
}

// ---------------- launch ----------------
extern "C" void kernel_launch(void* const* d_in, const int* in_sizes, int n_in,
                              void* d_out, int out_size) {
    const float* x   = (const float*)d_in[0];
    const int*   ei  = (const int*)d_in[1];     // int32! (JAX x64 disabled)
    const int*   eli = (const int*)d_in[2];     // int32!
    const float* W1  = (const float*)d_in[3];
    const float* b1  = (const float*)d_in[4];
    const float* W2  = (const float*)d_in[5];
    const float* b2  = (const float*)d_in[6];
    float* out = (float*)d_out;
    (void)in_sizes; (void)n_in; (void)out_size;

    k_deg_init  <<<(N_NODES + 255) / 256, 256>>>();
    k_deg_count <<<(N_EDGES + 255) / 256, 256>>>(ei);
    k_dinv      <<<(N_NODES + 255) / 256, 256>>>();
    k_scale_seed<<<(N_NODES * (IN_C / 4) + 255) / 256, 256>>>(x);

    k_scatter1  <<<(unsigned)((N_EDGES * 32u + 255u) / 256u), 256>>>(ei);

    dim3 g1((N_NODES + 63) / 64, HID1 / 64);
    k_gemm1     <<<g1, 256>>>(W1, b1);
    k_gemm2     <<<(N_NODES + 127) / 128, 256>>>(W2);

    k_scatter2  <<<(unsigned)((N_EDGES * 8u + 255u) / 256u), 256>>>(ei);

    k_z         <<<(N_NODES * (HID2 / 4) + 255) / 256, 256>>>(b2);
    k_decode    <<<(N_LABEL * 32 + 255) / 256, 256>>>(eli, out);
}

// round 4
// speedup vs baseline: 2.4783x; 2.4783x over previous
#include <cuda_runtime.h>

#define N_NODES 50000
#define N_EDGES 1600000
#define N_LABEL 200000
#define IN_C    128
#define HID1    256
#define HID2    32

#define SCAN_BLK 1024
#define N_SCAN_BLOCKS ((N_NODES + SCAN_BLK - 1) / SCAN_BLK)   // 49

// ---------------- device scratch ----------------
__device__ __align__(256) int   g_cnt   [N_NODES];
__device__ __align__(256) int   g_rowptr[N_NODES + 1];
__device__ __align__(256) int   g_cursor[N_NODES];
__device__ __align__(256) int   g_csrc  [N_EDGES];
__device__ __align__(256) int   g_bsum  [64];
__device__ __align__(256) int   g_boff  [64];
__device__ __align__(256) float g_dinv  [N_NODES];
__device__ __align__(256) float g_xs    [N_NODES * IN_C];   // dinv[i]*x[i]
__device__ __align__(256) float g_S1    [N_NODES * IN_C];
__device__ __align__(256) float g_h1    [N_NODES * HID1];
__device__ __align__(256) float g_ts    [N_NODES * HID2];   // dinv[i]*(h1@W2)
__device__ __align__(256) float g_z     [N_NODES * HID2];

// ---------------- CSR build ----------------
__global__ void k_zero_cnt() {
    int i = blockIdx.x * blockDim.x + threadIdx.x;
    if (i < N_NODES) g_cnt[i] = 0;
}

__global__ void k_hist(const int* __restrict__ ei) {
    int e = blockIdx.x * blockDim.x + threadIdx.x;
    if (e < N_EDGES) atomicAdd(&g_cnt[ei[N_EDGES + e]], 1);
}

// per-block inclusive scan -> exclusive rowptr (block-local) + block sums
__global__ void k_scan1() {
    __shared__ int sh[SCAN_BLK];
    int i = blockIdx.x * SCAN_BLK + threadIdx.x;
    int v = (i < N_NODES) ? g_cnt[i] : 0;
    sh[threadIdx.x] = v;
    __syncthreads();
#pragma unroll
    for (int off = 1; off < SCAN_BLK; off <<= 1) {
        int t = (threadIdx.x >= off) ? sh[threadIdx.x - off] : 0;
        __syncthreads();
        sh[threadIdx.x] += t;
        __syncthreads();
    }
    if (i < N_NODES) g_rowptr[i] = sh[threadIdx.x] - v;   // exclusive within block
    if (threadIdx.x == SCAN_BLK - 1) g_bsum[blockIdx.x] = sh[SCAN_BLK - 1];
}

__global__ void k_scan2() {   // 1 block, 64 threads: exclusive scan of block sums
    __shared__ int sh[64];
    int v = (threadIdx.x < N_SCAN_BLOCKS) ? g_bsum[threadIdx.x] : 0;
    sh[threadIdx.x] = v;
    __syncthreads();
#pragma unroll
    for (int off = 1; off < 64; off <<= 1) {
        int t = (threadIdx.x >= off) ? sh[threadIdx.x - off] : 0;
        __syncthreads();
        sh[threadIdx.x] += t;
        __syncthreads();
    }
    g_boff[threadIdx.x] = sh[threadIdx.x] - v;
}

// finalize rowptr, init cursor, compute dinv = rsqrt(indeg+1)
__global__ void k_scan3() {
    int i = blockIdx.x * blockDim.x + threadIdx.x;
    if (i < N_NODES) {
        int r = g_rowptr[i] + g_boff[i >> 10];
        g_rowptr[i] = r;
        g_cursor[i] = r;
        g_dinv[i]   = rsqrtf((float)(g_cnt[i] + 1));
    }
    if (i == 0) g_rowptr[N_NODES] = N_EDGES;
}

__global__ void k_fill(const int* __restrict__ ei) {
    int e = blockIdx.x * blockDim.x + threadIdx.x;
    if (e < N_EDGES) {
        int dst = ei[N_EDGES + e];
        int pos = atomicAdd(&g_cursor[dst], 1);
        g_csrc[pos] = ei[e];
    }
}

// ---------------- xs = dinv[i]*x[i] ----------------
__global__ void k_scale(const float* __restrict__ x) {
    int t = blockIdx.x * blockDim.x + threadIdx.x;       // N_NODES*32 float4s
    if (t < N_NODES * (IN_C / 4)) {
        int i = t >> 5;
        float di = g_dinv[i];
        float4 v = ((const float4*)x)[t];
        v.x *= di; v.y *= di; v.z *= di; v.w *= di;
        ((float4*)g_xs)[t] = v;
    }
}

// ---------------- conv1 aggregation (gather): S1[i] = xs[i] + sum_in xs[src]
// one warp per node; lane holds one float4 of the 128-dim row
__global__ void k_agg1() {
    int w = (blockIdx.x * blockDim.x + threadIdx.x) >> 5;
    if (w >= N_NODES) return;
    int lane = threadIdx.x & 31;
    int beg = g_rowptr[w], end = g_rowptr[w + 1];
    float4 acc = ((const float4*)g_xs)[w * 32 + lane];   // self loop
    int j = beg;
    for (; j + 1 < end; j += 2) {
        int s0 = g_csrc[j], s1 = g_csrc[j + 1];
        float4 v0 = ((const float4*)g_xs)[s0 * 32 + lane];
        float4 v1 = ((const float4*)g_xs)[s1 * 32 + lane];
        acc.x += v0.x; acc.y += v0.y; acc.z += v0.z; acc.w += v0.w;
        acc.x += v1.x; acc.y += v1.y; acc.z += v1.z; acc.w += v1.w;
    }
    if (j < end) {
        float4 v = ((const float4*)g_xs)[g_csrc[j] * 32 + lane];
        acc.x += v.x; acc.y += v.y; acc.z += v.z; acc.w += v.w;
    }
    ((float4*)g_S1)[w * 32 + lane] = acc;
}

// ---------------- GEMM1: h1 = relu(dinv[i]*(S1 @ W1) + b1)   [50000x128]x[128x256]
__global__ void k_gemm1(const float* __restrict__ W, const float* __restrict__ b1) {
    __shared__ float As[16][64];   // transposed [k][row]
    __shared__ float Bs[16][64];
    const int tid   = threadIdx.x;
    const int tileM = blockIdx.x * 64;
    const int tileN = blockIdx.y * 64;
    const int tx = tid & 15, ty = tid >> 4;
    const int ar = tid >> 2;
    const int ac = (tid & 3) * 4;
    const int br = tid >> 4;
    const int bc = (tid & 15) * 4;
    float acc[4][4] = {};

    for (int k0 = 0; k0 < IN_C; k0 += 16) {
        float4 av = make_float4(0.f, 0.f, 0.f, 0.f);
        int grow = tileM + ar;
        if (grow < N_NODES) av = *(const float4*)&g_S1[grow * IN_C + k0 + ac];
        As[ac + 0][ar] = av.x; As[ac + 1][ar] = av.y;
        As[ac + 2][ar] = av.z; As[ac + 3][ar] = av.w;
        *(float4*)&Bs[br][bc] = *(const float4*)&W[(k0 + br) * HID1 + tileN + bc];
        __syncthreads();
#pragma unroll
        for (int kk = 0; kk < 16; kk++) {
            float4 a  = *(const float4*)&As[kk][ty * 4];
            float4 bb = *(const float4*)&Bs[kk][tx * 4];
            float aa[4] = {a.x, a.y, a.z, a.w};
            float bv[4] = {bb.x, bb.y, bb.z, bb.w};
#pragma unroll
            for (int i = 0; i < 4; i++)
#pragma unroll
                for (int jj = 0; jj < 4; jj++) acc[i][jj] += aa[i] * bv[jj];
        }
        __syncthreads();
    }

    float4 bcol = *(const float4*)&b1[tileN + tx * 4];
    float bv[4] = {bcol.x, bcol.y, bcol.z, bcol.w};
#pragma unroll
    for (int i = 0; i < 4; i++) {
        int r = tileM + ty * 4 + i;
        if (r < N_NODES) {
            float di = g_dinv[r];
            float4 o;
            o.x = fmaxf(di * acc[i][0] + bv[0], 0.f);
            o.y = fmaxf(di * acc[i][1] + bv[1], 0.f);
            o.z = fmaxf(di * acc[i][2] + bv[2], 0.f);
            o.w = fmaxf(di * acc[i][3] + bv[3], 0.f);
            *(float4*)&g_h1[r * HID1 + tileN + tx * 4] = o;
        }
    }
}

// ---------------- GEMM2: ts = dinv[i]*(h1 @ W2)   [50000x256]x[256x32]
__global__ void k_gemm2(const float* __restrict__ W2) {
    __shared__ float As[128][33];
    __shared__ float Bs[32][32];
    const int tid   = threadIdx.x;
    const int tileM = blockIdx.x * 128;
    const int tx = tid & 7, ty = tid >> 3;
    float acc[4][4] = {};

    for (int k0 = 0; k0 < HID1; k0 += 32) {
#pragma unroll
        for (int i = 0; i < 4; i++) {
            int idx = tid + i * 256;
            int r   = idx >> 3;
            int c4  = (idx & 7) * 4;
            int grow = tileM + r;
            float4 v = make_float4(0.f, 0.f, 0.f, 0.f);
            if (grow < N_NODES) v = *(const float4*)&g_h1[grow * HID1 + k0 + c4];
            As[r][c4 + 0] = v.x; As[r][c4 + 1] = v.y;
            As[r][c4 + 2] = v.z; As[r][c4 + 3] = v.w;
        }
        {
            int kr = tid >> 3, c4 = (tid & 7) * 4;
            *(float4*)&Bs[kr][c4] = *(const float4*)&W2[(k0 + kr) * HID2 + c4];
        }
        __syncthreads();
#pragma unroll
        for (int kk = 0; kk < 32; kk++) {
            float4 bb = *(const float4*)&Bs[kk][tx * 4];
            float bv[4] = {bb.x, bb.y, bb.z, bb.w};
#pragma unroll
            for (int i = 0; i < 4; i++) {
                float a = As[ty * 4 + i][kk];
#pragma unroll
                for (int jj = 0; jj < 4; jj++) acc[i][jj] += a * bv[jj];
            }
        }
        __syncthreads();
    }

#pragma unroll
    for (int i = 0; i < 4; i++) {
        int r = tileM + ty * 4 + i;
        if (r < N_NODES) {
            float di = g_dinv[r];
            float4 o = make_float4(di * acc[i][0], di * acc[i][1],
                                   di * acc[i][2], di * acc[i][3]);
            *(float4*)&g_ts[r * HID2 + tx * 4] = o;
        }
    }
}

// ---------------- conv2 aggregation + z: z[i] = dinv[i]*(ts[i]+sum ts[src]) + b2
// one warp per node; lane holds one float of the 32-dim row
__global__ void k_agg2(const float* __restrict__ b2) {
    int w = (blockIdx.x * blockDim.x + threadIdx.x) >> 5;
    if (w >= N_NODES) return;
    int lane = threadIdx.x & 31;
    int beg = g_rowptr[w], end = g_rowptr[w + 1];
    float acc = g_ts[w * 32 + lane];                      // self loop
    int j = beg;
    for (; j + 1 < end; j += 2) {
        int s0 = g_csrc[j], s1 = g_csrc[j + 1];
        acc += g_ts[s0 * 32 + lane];
        acc += g_ts[s1 * 32 + lane];
    }
    if (j < end) acc += g_ts[g_csrc[j] * 32 + lane];
    g_z[w * 32 + lane] = g_dinv[w] * acc + b2[lane];
}

// ---------------- decode: out[k] = dot(z[a], z[b]); one warp per label edge
__global__ void k_decode(const int* __restrict__ eli, float* __restrict__ out) {
    int t = blockIdx.x * blockDim.x + threadIdx.x;
    int k = t >> 5;
    if (k >= N_LABEL) return;
    int lane = t & 31;
    int a = eli[k];
    int b = eli[N_LABEL + k];
    float p = g_z[a * 32 + lane] * g_z[b * 32 + lane];
#pragma unroll
    for (int off = 16; off; off >>= 1) p += __shfl_xor_sync(0xffffffffu, p, off);
    if (lane == 0) out[k] = p;
}

// ---------------- launch ----------------
extern "C" void kernel_launch(void* const* d_in, const int* in_sizes, int n_in,
                              void* d_out, int out_size) {
    const float* x   = (const float*)d_in[0];
    const int*   ei  = (const int*)d_in[1];     // int32 (JAX x64 disabled)
    const int*   eli = (const int*)d_in[2];
    const float* W1  = (const float*)d_in[3];
    const float* b1  = (const float*)d_in[4];
    const float* W2  = (const float*)d_in[5];
    const float* b2  = (const float*)d_in[6];
    float* out = (float*)d_out;
    (void)in_sizes; (void)n_in; (void)out_size;

    // CSR build (by dst)
    k_zero_cnt<<<(N_NODES + 255) / 256, 256>>>();
    k_hist    <<<(N_EDGES + 255) / 256, 256>>>(ei);
    k_scan1   <<<N_SCAN_BLOCKS, SCAN_BLK>>>();
    k_scan2   <<<1, 64>>>();
    k_scan3   <<<(N_NODES + 255) / 256, 256>>>();
    k_fill    <<<(N_EDGES + 255) / 256, 256>>>(ei);

    // feature pipeline
    k_scale   <<<(N_NODES * (IN_C / 4) + 255) / 256, 256>>>(x);
    k_agg1    <<<(N_NODES * 32 + 255) / 256, 256>>>();

    dim3 g1((N_NODES + 63) / 64, HID1 / 64);
    k_gemm1   <<<g1, 256>>>(W1, b1);
    k_gemm2   <<<(N_NODES + 127) / 128, 256>>>(W2);

    k_agg2    <<<(N_NODES * 32 + 255) / 256, 256>>>(b2);
    k_decode  <<<(N_LABEL * 32 + 255) / 256, 256>>>(eli, out);
}

// round 5
// speedup vs baseline: 3.3534x; 1.3531x over previous
#include <cuda_runtime.h>

#define N_NODES 50000
#define N_EDGES 1600000
#define N_LABEL 200000
#define IN_C    128
#define HID1    256
#define HID2    32

#define SCAN_BLK 1024
#define N_SCAN_BLOCKS ((N_NODES + SCAN_BLK - 1) / SCAN_BLK)   // 49

// ---------------- device scratch ----------------
__device__ __align__(256) int   g_cnt   [N_NODES];
__device__ __align__(256) int   g_rowptr[N_NODES + 1];
__device__ __align__(256) int   g_cursor[N_NODES];
__device__ __align__(256) int   g_csrc  [N_EDGES];
__device__ __align__(256) int   g_bsum  [64];
__device__ __align__(256) int   g_boff  [64];
__device__ __align__(256) float g_dinv  [N_NODES];
__device__ __align__(256) float g_xs    [N_NODES * IN_C];
__device__ __align__(256) float g_S1    [N_NODES * IN_C];
__device__ __align__(256) float g_h1    [N_NODES * HID1];
__device__ __align__(256) float g_ts    [N_NODES * HID2];
__device__ __align__(256) float g_z     [N_NODES * HID2];

// ---------------- tf32 helpers ----------------
__device__ __forceinline__ unsigned f2tf32(float f) {
    unsigned r;
    asm("cvt.rna.tf32.f32 %0, %1;" : "=r"(r) : "f"(f));
    return r;
}
__device__ __forceinline__ void mma_tf32(float* c, unsigned a0, unsigned a1,
                                         unsigned a2, unsigned a3,
                                         unsigned b0, unsigned b1) {
    asm volatile(
        "mma.sync.aligned.m16n8k8.row.col.f32.tf32.tf32.f32 "
        "{%0,%1,%2,%3}, {%4,%5,%6,%7}, {%8,%9}, {%0,%1,%2,%3};"
        : "+f"(c[0]), "+f"(c[1]), "+f"(c[2]), "+f"(c[3])
        : "r"(a0), "r"(a1), "r"(a2), "r"(a3), "r"(b0), "r"(b1));
}

// ---------------- CSR build ----------------
__global__ void k_zero_cnt() {
    int i = blockIdx.x * blockDim.x + threadIdx.x;
    if (i < N_NODES) g_cnt[i] = 0;
}

__global__ void k_hist(const int* __restrict__ ei) {
    int e = blockIdx.x * blockDim.x + threadIdx.x;
    if (e < N_EDGES) atomicAdd(&g_cnt[ei[N_EDGES + e]], 1);
}

__global__ void k_scan1() {
    __shared__ int sh[SCAN_BLK];
    int i = blockIdx.x * SCAN_BLK + threadIdx.x;
    int v = (i < N_NODES) ? g_cnt[i] : 0;
    sh[threadIdx.x] = v;
    __syncthreads();
#pragma unroll
    for (int off = 1; off < SCAN_BLK; off <<= 1) {
        int t = (threadIdx.x >= off) ? sh[threadIdx.x - off] : 0;
        __syncthreads();
        sh[threadIdx.x] += t;
        __syncthreads();
    }
    if (i < N_NODES) g_rowptr[i] = sh[threadIdx.x] - v;
    if (threadIdx.x == SCAN_BLK - 1) g_bsum[blockIdx.x] = sh[SCAN_BLK - 1];
}

__global__ void k_scan2() {
    __shared__ int sh[64];
    int v = (threadIdx.x < N_SCAN_BLOCKS) ? g_bsum[threadIdx.x] : 0;
    sh[threadIdx.x] = v;
    __syncthreads();
#pragma unroll
    for (int off = 1; off < 64; off <<= 1) {
        int t = (threadIdx.x >= off) ? sh[threadIdx.x - off] : 0;
        __syncthreads();
        sh[threadIdx.x] += t;
        __syncthreads();
    }
    g_boff[threadIdx.x] = sh[threadIdx.x] - v;
}

__global__ void k_scan3() {
    int i = blockIdx.x * blockDim.x + threadIdx.x;
    if (i < N_NODES) {
        int r = g_rowptr[i] + g_boff[i >> 10];
        g_rowptr[i] = r;
        g_cursor[i] = r;
        g_dinv[i]   = rsqrtf((float)(g_cnt[i] + 1));
    }
    if (i == 0) g_rowptr[N_NODES] = N_EDGES;
}

__global__ void k_fill(const int* __restrict__ ei) {
    int e = blockIdx.x * blockDim.x + threadIdx.x;
    if (e < N_EDGES) {
        int dst = ei[N_EDGES + e];
        int pos = atomicAdd(&g_cursor[dst], 1);
        g_csrc[pos] = ei[e];
    }
}

// ---------------- xs = dinv[i]*x[i] ----------------
__global__ void k_scale(const float* __restrict__ x) {
    int t = blockIdx.x * blockDim.x + threadIdx.x;
    if (t < N_NODES * (IN_C / 4)) {
        int i = t >> 5;
        float di = g_dinv[i];
        float4 v = ((const float4*)x)[t];
        v.x *= di; v.y *= di; v.z *= di; v.w *= di;
        ((float4*)g_xs)[t] = v;
    }
}

// ---------------- conv1 gather: S1[i] = xs[i] + sum_in xs[src] ----------------
__global__ void k_agg1() {
    int w = (blockIdx.x * blockDim.x + threadIdx.x) >> 5;
    if (w >= N_NODES) return;
    int lane = threadIdx.x & 31;
    int beg = g_rowptr[w], end = g_rowptr[w + 1];
    float4 acc = ((const float4*)g_xs)[w * 32 + lane];
    int j = beg;
    for (; j + 1 < end; j += 2) {
        int s0 = g_csrc[j], s1 = g_csrc[j + 1];
        float4 v0 = ((const float4*)g_xs)[s0 * 32 + lane];
        float4 v1 = ((const float4*)g_xs)[s1 * 32 + lane];
        acc.x += v0.x; acc.y += v0.y; acc.z += v0.z; acc.w += v0.w;
        acc.x += v1.x; acc.y += v1.y; acc.z += v1.z; acc.w += v1.w;
    }
    if (j < end) {
        float4 v = ((const float4*)g_xs)[g_csrc[j] * 32 + lane];
        acc.x += v.x; acc.y += v.y; acc.z += v.z; acc.w += v.w;
    }
    ((float4*)g_S1)[w * 32 + lane] = acc;
}

// ---------------- GEMM1 (tf32 MMA): h1 = relu(dinv*(S1@W1)+b1)  [50000x128]x[128x256]
// block 256 thr = 8 warps (4M x 2N); BM=128 BN=64 BK=16; warp = 32x32 (2 m16 x 4 n8)
#define G1_AS 18   // padded stride (conflict-free frag loads)
#define G1_BS 72
__global__ void k_gemm1(const float* __restrict__ W, const float* __restrict__ b1) {
    __shared__ unsigned As[128 * G1_AS];
    __shared__ unsigned Bs[16 * G1_BS];
    const int tid   = threadIdx.x;
    const int tileM = blockIdx.x * 128;
    const int tileN = blockIdx.y * 64;
    const int warpId = tid >> 5, lane = tid & 31;
    const int warpM = warpId & 3, warpN = warpId >> 2;
    const int gid = lane >> 2, tg = lane & 3;

    float acc[2][4][4] = {};

    for (int k0 = 0; k0 < IN_C; k0 += 16) {
        // load A tile 128x16 (8 elems/thread = 2 float4)
        {
            int r  = tid >> 1;
            int c0 = (tid & 1) * 8;
            int grow = tileM + r;
            float4 v0 = make_float4(0.f,0.f,0.f,0.f), v1 = v0;
            if (grow < N_NODES) {
                v0 = *(const float4*)&g_S1[grow * IN_C + k0 + c0];
                v1 = *(const float4*)&g_S1[grow * IN_C + k0 + c0 + 4];
            }
            unsigned* a = &As[r * G1_AS + c0];
            a[0]=f2tf32(v0.x); a[1]=f2tf32(v0.y); a[2]=f2tf32(v0.z); a[3]=f2tf32(v0.w);
            a[4]=f2tf32(v1.x); a[5]=f2tf32(v1.y); a[6]=f2tf32(v1.z); a[7]=f2tf32(v1.w);
        }
        // load B tile 16x64 (4 elems/thread)
        {
            int r = tid >> 4;
            int c = (tid & 15) * 4;
            float4 v = *(const float4*)&W[(k0 + r) * HID1 + tileN + c];
            unsigned* b = &Bs[r * G1_BS + c];
            b[0]=f2tf32(v.x); b[1]=f2tf32(v.y); b[2]=f2tf32(v.z); b[3]=f2tf32(v.w);
        }
        __syncthreads();
#pragma unroll
        for (int ks = 0; ks < 16; ks += 8) {
            unsigned a[2][4];
#pragma unroll
            for (int mt = 0; mt < 2; mt++) {
                int rb = warpM * 32 + mt * 16;
                a[mt][0] = As[(rb + gid    ) * G1_AS + ks + tg    ];
                a[mt][1] = As[(rb + gid + 8) * G1_AS + ks + tg    ];
                a[mt][2] = As[(rb + gid    ) * G1_AS + ks + tg + 4];
                a[mt][3] = As[(rb + gid + 8) * G1_AS + ks + tg + 4];
            }
#pragma unroll
            for (int nt = 0; nt < 4; nt++) {
                int cb = warpN * 32 + nt * 8;
                unsigned b0 = Bs[(ks + tg    ) * G1_BS + cb + gid];
                unsigned b1v= Bs[(ks + tg + 4) * G1_BS + cb + gid];
#pragma unroll
                for (int mt = 0; mt < 2; mt++)
                    mma_tf32(acc[mt][nt], a[mt][0], a[mt][1], a[mt][2], a[mt][3], b0, b1v);
            }
        }
        __syncthreads();
    }

    // epilogue: relu(dinv*acc + bias)
#pragma unroll
    for (int mt = 0; mt < 2; mt++) {
        int r0 = tileM + warpM * 32 + mt * 16 + gid;
        int r1 = r0 + 8;
        float d0 = (r0 < N_NODES) ? g_dinv[r0] : 0.f;
        float d1 = (r1 < N_NODES) ? g_dinv[r1] : 0.f;
#pragma unroll
        for (int nt = 0; nt < 4; nt++) {
            int c = tileN + warpN * 32 + nt * 8 + tg * 2;
            float bb0 = b1[c], bb1 = b1[c + 1];
            if (r0 < N_NODES) {
                float2 o;
                o.x = fmaxf(d0 * acc[mt][nt][0] + bb0, 0.f);
                o.y = fmaxf(d0 * acc[mt][nt][1] + bb1, 0.f);
                *(float2*)&g_h1[r0 * HID1 + c] = o;
            }
            if (r1 < N_NODES) {
                float2 o;
                o.x = fmaxf(d1 * acc[mt][nt][2] + bb0, 0.f);
                o.y = fmaxf(d1 * acc[mt][nt][3] + bb1, 0.f);
                *(float2*)&g_h1[r1 * HID1 + c] = o;
            }
        }
    }
}

// ---------------- GEMM2 (tf32 MMA): ts = dinv*(h1@W2)  [50000x256]x[256x32]
// block 256 thr = 8 warps (8M x 1N); BM=128 BN=32 BK=32; warp = 16x32 (1 m16 x 4 n8)
#define G2_AS 36
#define G2_BS 72
__global__ void k_gemm2(const float* __restrict__ W2) {
    __shared__ unsigned As[128 * G2_AS];
    __shared__ unsigned Bs[32 * G2_BS];
    const int tid   = threadIdx.x;
    const int tileM = blockIdx.x * 128;
    const int warpId = tid >> 5, lane = tid & 31;
    const int gid = lane >> 2, tg = lane & 3;

    float acc[4][4] = {};

    for (int k0 = 0; k0 < HID1; k0 += 32) {
        // load A tile 128x32 (16 elems/thread = 4 float4)
#pragma unroll
        for (int i = 0; i < 4; i++) {
            int idx = tid + i * 256;
            int r   = idx >> 3;
            int c0  = (idx & 7) * 4;
            int grow = tileM + r;
            float4 v = make_float4(0.f,0.f,0.f,0.f);
            if (grow < N_NODES) v = *(const float4*)&g_h1[grow * HID1 + k0 + c0];
            unsigned* a = &As[r * G2_AS + c0];
            a[0]=f2tf32(v.x); a[1]=f2tf32(v.y); a[2]=f2tf32(v.z); a[3]=f2tf32(v.w);
        }
        // load B tile 32x32 (4 elems/thread)
        {
            int r = tid >> 3;
            int c = (tid & 7) * 4;
            float4 v = *(const float4*)&W2[(k0 + r) * HID2 + c];
            unsigned* b = &Bs[r * G2_BS + c];
            b[0]=f2tf32(v.x); b[1]=f2tf32(v.y); b[2]=f2tf32(v.z); b[3]=f2tf32(v.w);
        }
        __syncthreads();
#pragma unroll
        for (int ks = 0; ks < 32; ks += 8) {
            int rb = warpId * 16;
            unsigned a0 = As[(rb + gid    ) * G2_AS + ks + tg    ];
            unsigned a1 = As[(rb + gid + 8) * G2_AS + ks + tg    ];
            unsigned a2 = As[(rb + gid    ) * G2_AS + ks + tg + 4];
            unsigned a3 = As[(rb + gid + 8) * G2_AS + ks + tg + 4];
#pragma unroll
            for (int nt = 0; nt < 4; nt++) {
                int cb = nt * 8;
                unsigned b0 = Bs[(ks + tg    ) * G2_BS + cb + gid];
                unsigned b1v= Bs[(ks + tg + 4) * G2_BS + cb + gid];
                mma_tf32(acc[nt], a0, a1, a2, a3, b0, b1v);
            }
        }
        __syncthreads();
    }

    int r0 = tileM + warpId * 16 + gid;
    int r1 = r0 + 8;
    float d0 = (r0 < N_NODES) ? g_dinv[r0] : 0.f;
    float d1 = (r1 < N_NODES) ? g_dinv[r1] : 0.f;
#pragma unroll
    for (int nt = 0; nt < 4; nt++) {
        int c = nt * 8 + tg * 2;
        if (r0 < N_NODES) {
            float2 o = make_float2(d0 * acc[nt][0], d0 * acc[nt][1]);
            *(float2*)&g_ts[r0 * HID2 + c] = o;
        }
        if (r1 < N_NODES) {
            float2 o = make_float2(d1 * acc[nt][2], d1 * acc[nt][3]);
            *(float2*)&g_ts[r1 * HID2 + c] = o;
        }
    }
}

// ---------------- conv2 gather + z ----------------
__global__ void k_agg2(const float* __restrict__ b2) {
    int w = (blockIdx.x * blockDim.x + threadIdx.x) >> 5;
    if (w >= N_NODES) return;
    int lane = threadIdx.x & 31;
    int beg = g_rowptr[w], end = g_rowptr[w + 1];
    float acc = g_ts[w * 32 + lane];
    int j = beg;
    for (; j + 1 < end; j += 2) {
        int s0 = g_csrc[j], s1 = g_csrc[j + 1];
        acc += g_ts[s0 * 32 + lane];
        acc += g_ts[s1 * 32 + lane];
    }
    if (j < end) acc += g_ts[g_csrc[j] * 32 + lane];
    g_z[w * 32 + lane] = g_dinv[w] * acc + b2[lane];
}

// ---------------- decode ----------------
__global__ void k_decode(const int* __restrict__ eli, float* __restrict__ out) {
    int t = blockIdx.x * blockDim.x + threadIdx.x;
    int k = t >> 5;
    if (k >= N_LABEL) return;
    int lane = t & 31;
    int a = eli[k];
    int b = eli[N_LABEL + k];
    float p = g_z[a * 32 + lane] * g_z[b * 32 + lane];
#pragma unroll
    for (int off = 16; off; off >>= 1) p += __shfl_xor_sync(0xffffffffu, p, off);
    if (lane == 0) out[k] = p;
}

// ---------------- launch ----------------
extern "C" void kernel_launch(void* const* d_in, const int* in_sizes, int n_in,
                              void* d_out, int out_size) {
    const float* x   = (const float*)d_in[0];
    const int*   ei  = (const int*)d_in[1];     // int32 (JAX x64 disabled)
    const int*   eli = (const int*)d_in[2];
    const float* W1  = (const float*)d_in[3];
    const float* b1  = (const float*)d_in[4];
    const float* W2  = (const float*)d_in[5];
    const float* b2  = (const float*)d_in[6];
    float* out = (float*)d_out;
    (void)in_sizes; (void)n_in; (void)out_size;

    k_zero_cnt<<<(N_NODES + 255) / 256, 256>>>();
    k_hist    <<<(N_EDGES + 255) / 256, 256>>>(ei);
    k_scan1   <<<N_SCAN_BLOCKS, SCAN_BLK>>>();
    k_scan2   <<<1, 64>>>();
    k_scan3   <<<(N_NODES + 255) / 256, 256>>>();
    k_fill    <<<(N_EDGES + 255) / 256, 256>>>(ei);

    k_scale   <<<(N_NODES * (IN_C / 4) + 255) / 256, 256>>>(x);
    k_agg1    <<<(N_NODES * 32 + 255) / 256, 256>>>();

    dim3 g1((N_NODES + 127) / 128, HID1 / 64);
    k_gemm1   <<<g1, 256>>>(W1, b1);
    k_gemm2   <<<(N_NODES + 127) / 128, 256>>>(W2);

    k_agg2    <<<(N_NODES * 32 + 255) / 256, 256>>>(b2);
    k_decode  <<<(N_LABEL * 32 + 255) / 256, 256>>>(eli, out);
}

// round 6
// speedup vs baseline: 3.6023x; 1.0742x over previous
#include <cuda_runtime.h>

#define N_NODES 50000
#define N_EDGES 1600000
#define N_LABEL 200000
#define IN_C    128
#define HID1    256
#define HID2    32

#define SCAN_BLK 1024
#define N_SCAN_BLOCKS ((N_NODES + SCAN_BLK - 1) / SCAN_BLK)   // 49

// ---------------- device scratch ----------------
__device__ __align__(256) int   g_cnt   [N_NODES];
__device__ __align__(256) int   g_rowptr[N_NODES + 1];
__device__ __align__(256) int   g_cursor[N_NODES];
__device__ __align__(256) int   g_csrc  [N_EDGES];
__device__ __align__(256) int   g_bsum  [64];
__device__ __align__(256) int   g_boff  [64];
__device__ __align__(256) float g_dinv  [N_NODES];
__device__ __align__(256) float g_S1    [N_NODES * IN_C];
__device__ __align__(256) float g_h1    [N_NODES * HID1];
__device__ __align__(256) float g_ts    [N_NODES * HID2];
__device__ __align__(256) float g_z     [N_NODES * HID2];

// ---------------- tf32 helpers ----------------
__device__ __forceinline__ unsigned f2tf32(float f) {
    unsigned r;
    asm("cvt.rna.tf32.f32 %0, %1;" : "=r"(r) : "f"(f));
    return r;
}
__device__ __forceinline__ void mma_tf32(float* c, unsigned a0, unsigned a1,
                                         unsigned a2, unsigned a3,
                                         unsigned b0, unsigned b1) {
    asm volatile(
        "mma.sync.aligned.m16n8k8.row.col.f32.tf32.tf32.f32 "
        "{%0,%1,%2,%3}, {%4,%5,%6,%7}, {%8,%9}, {%0,%1,%2,%3};"
        : "+f"(c[0]), "+f"(c[1]), "+f"(c[2]), "+f"(c[3])
        : "r"(a0), "r"(a1), "r"(a2), "r"(a3), "r"(b0), "r"(b1));
}

// ---------------- CSR build ----------------
__global__ void k_zero_cnt() {
    int i = blockIdx.x * blockDim.x + threadIdx.x;
    if (i < N_NODES) g_cnt[i] = 0;
}

__global__ void k_hist(const int* __restrict__ ei) {
    int e = blockIdx.x * blockDim.x + threadIdx.x;
    if (e < N_EDGES) atomicAdd(&g_cnt[ei[N_EDGES + e]], 1);
}

// scan + dinv (cnt is final here)
__global__ void k_scan1() {
    __shared__ int sh[SCAN_BLK];
    int i = blockIdx.x * SCAN_BLK + threadIdx.x;
    int v = (i < N_NODES) ? g_cnt[i] : 0;
    if (i < N_NODES) g_dinv[i] = rsqrtf((float)(v + 1));
    sh[threadIdx.x] = v;
    __syncthreads();
#pragma unroll
    for (int off = 1; off < SCAN_BLK; off <<= 1) {
        int t = (threadIdx.x >= off) ? sh[threadIdx.x - off] : 0;
        __syncthreads();
        sh[threadIdx.x] += t;
        __syncthreads();
    }
    if (i < N_NODES) g_rowptr[i] = sh[threadIdx.x] - v;
    if (threadIdx.x == SCAN_BLK - 1) g_bsum[blockIdx.x] = sh[SCAN_BLK - 1];
}

__global__ void k_scan2() {
    __shared__ int sh[64];
    int v = (threadIdx.x < N_SCAN_BLOCKS) ? g_bsum[threadIdx.x] : 0;
    sh[threadIdx.x] = v;
    __syncthreads();
#pragma unroll
    for (int off = 1; off < 64; off <<= 1) {
        int t = (threadIdx.x >= off) ? sh[threadIdx.x - off] : 0;
        __syncthreads();
        sh[threadIdx.x] += t;
        __syncthreads();
    }
    g_boff[threadIdx.x] = sh[threadIdx.x] - v;
}

__global__ void k_scan3() {
    int i = blockIdx.x * blockDim.x + threadIdx.x;
    if (i < N_NODES) {
        int r = g_rowptr[i] + g_boff[i >> 10];
        g_rowptr[i] = r;
        g_cursor[i] = r;
    }
    if (i == 0) g_rowptr[N_NODES] = N_EDGES;
}

__global__ void k_fill(const int* __restrict__ ei) {
    int e = blockIdx.x * blockDim.x + threadIdx.x;
    if (e < N_EDGES) {
        int dst = ei[N_EDGES + e];
        int pos = atomicAdd(&g_cursor[dst], 1);
        g_csrc[pos] = ei[e];
    }
}

// ---------------- conv1 gather (inline dinv scaling):
// S1[i] = dinv[i]*x[i] + sum_in dinv[src]*x[src]
__global__ void k_agg1(const float* __restrict__ x) {
    int w = (blockIdx.x * blockDim.x + threadIdx.x) >> 5;
    if (w >= N_NODES) return;
    int lane = threadIdx.x & 31;
    int beg = g_rowptr[w], end = g_rowptr[w + 1];
    const float4* xv = (const float4*)x;

    float dw = g_dinv[w];
    float4 s = xv[w * 32 + lane];
    float4 acc = make_float4(dw * s.x, dw * s.y, dw * s.z, dw * s.w);

    int j = beg;
    for (; j + 3 < end; j += 4) {
        int s0 = g_csrc[j], s1 = g_csrc[j + 1], s2 = g_csrc[j + 2], s3 = g_csrc[j + 3];
        float d0 = g_dinv[s0], d1 = g_dinv[s1], d2 = g_dinv[s2], d3 = g_dinv[s3];
        float4 v0 = xv[s0 * 32 + lane];
        float4 v1 = xv[s1 * 32 + lane];
        float4 v2 = xv[s2 * 32 + lane];
        float4 v3 = xv[s3 * 32 + lane];
        acc.x += d0 * v0.x; acc.y += d0 * v0.y; acc.z += d0 * v0.z; acc.w += d0 * v0.w;
        acc.x += d1 * v1.x; acc.y += d1 * v1.y; acc.z += d1 * v1.z; acc.w += d1 * v1.w;
        acc.x += d2 * v2.x; acc.y += d2 * v2.y; acc.z += d2 * v2.z; acc.w += d2 * v2.w;
        acc.x += d3 * v3.x; acc.y += d3 * v3.y; acc.z += d3 * v3.z; acc.w += d3 * v3.w;
    }
    for (; j < end; j++) {
        int sj = g_csrc[j];
        float dj = g_dinv[sj];
        float4 v = xv[sj * 32 + lane];
        acc.x += dj * v.x; acc.y += dj * v.y; acc.z += dj * v.z; acc.w += dj * v.w;
    }
    ((float4*)g_S1)[w * 32 + lane] = acc;
}

// ---------------- GEMM1 (tf32 MMA): h1 = relu(dinv*(S1@W1)+b1)  [50000x128]x[128x256]
// 8 warps (4M x 2N); BM=128 BN=64 BK=32; warp = 32x32 (2 m16 x 4 n8)
#define G1_AS 36
#define G1_BS 72
__global__ void k_gemm1(const float* __restrict__ W, const float* __restrict__ b1) {
    __shared__ unsigned As[128 * G1_AS];
    __shared__ unsigned Bs[32 * G1_BS];
    const int tid   = threadIdx.x;
    const int tileM = blockIdx.x * 128;
    const int tileN = blockIdx.y * 64;
    const int warpId = tid >> 5, lane = tid & 31;
    const int warpM = warpId & 3, warpN = warpId >> 2;
    const int gid = lane >> 2, tg = lane & 3;

    float acc[2][4][4] = {};

    for (int k0 = 0; k0 < IN_C; k0 += 32) {
        // A tile 128x32: 16 elems/thread = 4 float4
#pragma unroll
        for (int i = 0; i < 4; i++) {
            int idx = tid + i * 256;
            int r   = idx >> 3;
            int c0  = (idx & 7) * 4;
            int grow = tileM + r;
            float4 v = make_float4(0.f,0.f,0.f,0.f);
            if (grow < N_NODES) v = *(const float4*)&g_S1[grow * IN_C + k0 + c0];
            unsigned* a = &As[r * G1_AS + c0];
            a[0]=f2tf32(v.x); a[1]=f2tf32(v.y); a[2]=f2tf32(v.z); a[3]=f2tf32(v.w);
        }
        // B tile 32x64: 8 elems/thread = 2 float4
#pragma unroll
        for (int i = 0; i < 2; i++) {
            int idx = tid + i * 256;
            int r   = idx >> 4;
            int c   = (idx & 15) * 4;
            float4 v = *(const float4*)&W[(k0 + r) * HID1 + tileN + c];
            unsigned* b = &Bs[r * G1_BS + c];
            b[0]=f2tf32(v.x); b[1]=f2tf32(v.y); b[2]=f2tf32(v.z); b[3]=f2tf32(v.w);
        }
        __syncthreads();
#pragma unroll
        for (int ks = 0; ks < 32; ks += 8) {
            unsigned a[2][4];
#pragma unroll
            for (int mt = 0; mt < 2; mt++) {
                int rb = warpM * 32 + mt * 16;
                a[mt][0] = As[(rb + gid    ) * G1_AS + ks + tg    ];
                a[mt][1] = As[(rb + gid + 8) * G1_AS + ks + tg    ];
                a[mt][2] = As[(rb + gid    ) * G1_AS + ks + tg + 4];
                a[mt][3] = As[(rb + gid + 8) * G1_AS + ks + tg + 4];
            }
#pragma unroll
            for (int nt = 0; nt < 4; nt++) {
                int cb = warpN * 32 + nt * 8;
                unsigned b0 = Bs[(ks + tg    ) * G1_BS + cb + gid];
                unsigned b1v= Bs[(ks + tg + 4) * G1_BS + cb + gid];
#pragma unroll
                for (int mt = 0; mt < 2; mt++)
                    mma_tf32(acc[mt][nt], a[mt][0], a[mt][1], a[mt][2], a[mt][3], b0, b1v);
            }
        }
        __syncthreads();
    }

#pragma unroll
    for (int mt = 0; mt < 2; mt++) {
        int r0 = tileM + warpM * 32 + mt * 16 + gid;
        int r1 = r0 + 8;
        float d0 = (r0 < N_NODES) ? g_dinv[r0] : 0.f;
        float d1 = (r1 < N_NODES) ? g_dinv[r1] : 0.f;
#pragma unroll
        for (int nt = 0; nt < 4; nt++) {
            int c = tileN + warpN * 32 + nt * 8 + tg * 2;
            float bb0 = b1[c], bb1 = b1[c + 1];
            if (r0 < N_NODES) {
                float2 o;
                o.x = fmaxf(d0 * acc[mt][nt][0] + bb0, 0.f);
                o.y = fmaxf(d0 * acc[mt][nt][1] + bb1, 0.f);
                *(float2*)&g_h1[r0 * HID1 + c] = o;
            }
            if (r1 < N_NODES) {
                float2 o;
                o.x = fmaxf(d1 * acc[mt][nt][2] + bb0, 0.f);
                o.y = fmaxf(d1 * acc[mt][nt][3] + bb1, 0.f);
                *(float2*)&g_h1[r1 * HID1 + c] = o;
            }
        }
    }
}

// ---------------- GEMM2 (tf32 MMA): ts = dinv*(h1@W2)  [50000x256]x[256x32]
#define G2_AS 36
#define G2_BS 72
__global__ void k_gemm2(const float* __restrict__ W2) {
    __shared__ unsigned As[128 * G2_AS];
    __shared__ unsigned Bs[32 * G2_BS];
    const int tid   = threadIdx.x;
    const int tileM = blockIdx.x * 128;
    const int warpId = tid >> 5, lane = tid & 31;
    const int gid = lane >> 2, tg = lane & 3;

    float acc[4][4] = {};

    for (int k0 = 0; k0 < HID1; k0 += 32) {
#pragma unroll
        for (int i = 0; i < 4; i++) {
            int idx = tid + i * 256;
            int r   = idx >> 3;
            int c0  = (idx & 7) * 4;
            int grow = tileM + r;
            float4 v = make_float4(0.f,0.f,0.f,0.f);
            if (grow < N_NODES) v = *(const float4*)&g_h1[grow * HID1 + k0 + c0];
            unsigned* a = &As[r * G2_AS + c0];
            a[0]=f2tf32(v.x); a[1]=f2tf32(v.y); a[2]=f2tf32(v.z); a[3]=f2tf32(v.w);
        }
        {
            int r = tid >> 3;
            int c = (tid & 7) * 4;
            float4 v = *(const float4*)&W2[(k0 + r) * HID2 + c];
            unsigned* b = &Bs[r * G2_BS + c];
            b[0]=f2tf32(v.x); b[1]=f2tf32(v.y); b[2]=f2tf32(v.z); b[3]=f2tf32(v.w);
        }
        __syncthreads();
#pragma unroll
        for (int ks = 0; ks < 32; ks += 8) {
            int rb = warpId * 16;
            unsigned a0 = As[(rb + gid    ) * G2_AS + ks + tg    ];
            unsigned a1 = As[(rb + gid + 8) * G2_AS + ks + tg    ];
            unsigned a2 = As[(rb + gid    ) * G2_AS + ks + tg + 4];
            unsigned a3 = As[(rb + gid + 8) * G2_AS + ks + tg + 4];
#pragma unroll
            for (int nt = 0; nt < 4; nt++) {
                int cb = nt * 8;
                unsigned b0 = Bs[(ks + tg    ) * G2_BS + cb + gid];
                unsigned b1v= Bs[(ks + tg + 4) * G2_BS + cb + gid];
                mma_tf32(acc[nt], a0, a1, a2, a3, b0, b1v);
            }
        }
        __syncthreads();
    }

    int r0 = tileM + warpId * 16 + gid;
    int r1 = r0 + 8;
    float d0 = (r0 < N_NODES) ? g_dinv[r0] : 0.f;
    float d1 = (r1 < N_NODES) ? g_dinv[r1] : 0.f;
#pragma unroll
    for (int nt = 0; nt < 4; nt++) {
        int c = nt * 8 + tg * 2;
        if (r0 < N_NODES) {
            float2 o = make_float2(d0 * acc[nt][0], d0 * acc[nt][1]);
            *(float2*)&g_ts[r0 * HID2 + c] = o;
        }
        if (r1 < N_NODES) {
            float2 o = make_float2(d1 * acc[nt][2], d1 * acc[nt][3]);
            *(float2*)&g_ts[r1 * HID2 + c] = o;
        }
    }
}

// ---------------- conv2 gather + z ----------------
__global__ void k_agg2(const float* __restrict__ b2) {
    int w = (blockIdx.x * blockDim.x + threadIdx.x) >> 5;
    if (w >= N_NODES) return;
    int lane = threadIdx.x & 31;
    int beg = g_rowptr[w], end = g_rowptr[w + 1];
    float acc = g_ts[w * 32 + lane];
    int j = beg;
    for (; j + 3 < end; j += 4) {
        int s0 = g_csrc[j], s1 = g_csrc[j + 1], s2 = g_csrc[j + 2], s3 = g_csrc[j + 3];
        acc += g_ts[s0 * 32 + lane];
        acc += g_ts[s1 * 32 + lane];
        acc += g_ts[s2 * 32 + lane];
        acc += g_ts[s3 * 32 + lane];
    }
    for (; j < end; j++) acc += g_ts[g_csrc[j] * 32 + lane];
    g_z[w * 32 + lane] = g_dinv[w] * acc + b2[lane];
}

// ---------------- decode ----------------
__global__ void k_decode(const int* __restrict__ eli, float* __restrict__ out) {
    int t = blockIdx.x * blockDim.x + threadIdx.x;
    int k = t >> 5;
    if (k >= N_LABEL) return;
    int lane = t & 31;
    int a = eli[k];
    int b = eli[N_LABEL + k];
    float p = g_z[a * 32 + lane] * g_z[b * 32 + lane];
#pragma unroll
    for (int off = 16; off; off >>= 1) p += __shfl_xor_sync(0xffffffffu, p, off);
    if (lane == 0) out[k] = p;
}

// ---------------- launch ----------------
extern "C" void kernel_launch(void* const* d_in, const int* in_sizes, int n_in,
                              void* d_out, int out_size) {
    const float* x   = (const float*)d_in[0];
    const int*   ei  = (const int*)d_in[1];     // int32 (JAX x64 disabled)
    const int*   eli = (const int*)d_in[2];
    const float* W1  = (const float*)d_in[3];
    const float* b1  = (const float*)d_in[4];
    const float* W2  = (const float*)d_in[5];
    const float* b2  = (const float*)d_in[6];
    float* out = (float*)d_out;
    (void)in_sizes; (void)n_in; (void)out_size;

    k_zero_cnt<<<(N_NODES + 255) / 256, 256>>>();
    k_hist    <<<(N_EDGES + 255) / 256, 256>>>(ei);
    k_scan1   <<<N_SCAN_BLOCKS, SCAN_BLK>>>();
    k_scan2   <<<1, 64>>>();
    k_scan3   <<<(N_NODES + 255) / 256, 256>>>();
    k_fill    <<<(N_EDGES + 255) / 256, 256>>>(ei);

    k_agg1    <<<(N_NODES * 32 + 255) / 256, 256>>>(x);

    dim3 g1((N_NODES + 127) / 128, HID1 / 64);
    k_gemm1   <<<g1, 256>>>(W1, b1);
    k_gemm2   <<<(N_NODES + 127) / 128, 256>>>(W2);

    k_agg2    <<<(N_NODES * 32 + 255) / 256, 256>>>(b2);
    k_decode  <<<(N_LABEL * 32 + 255) / 256, 256>>>(eli, out);
}